// round 3
// baseline (speedup 1.0000x reference)
#include <cuda_runtime.h>
#include <mma.h>
#include <math.h>

using namespace nvcuda;

#define NROWS 8192
#define DIM 512

// Scratch (module-load allocated; no cudaMalloc anywhere)
__device__ float g_Q [NROWS*DIM];
__device__ float g_K [NROWS*DIM];
__device__ float g_V [NROWS*DIM];
__device__ float g_XR[NROWS*DIM];
__device__ float g_H [NROWS*DIM];

typedef wmma::fragment<wmma::matrix_a,16,16,8,wmma::precision::tf32,wmma::row_major> FragA;
typedef wmma::fragment<wmma::matrix_b,16,16,8,wmma::precision::tf32,wmma::row_major> FragB;
typedef wmma::fragment<wmma::matrix_b,16,16,8,wmma::precision::tf32,wmma::col_major> FragBT;
typedef wmma::fragment<wmma::accumulator,16,16,8,float> FragC;

// ---------------------------------------------------------------------------
// Small GEMMs (M=8192, N=512, K=512): C = act(A @ B + bias), tf32x3 accuracy.
// BM=64, BN=128, BK=32, 256 threads, warp grid 4(M) x 2(N), warp tile 16x64.
// hi/lo split done ONCE at SMEM store; fragments load pre-split tiles.
// Dynamic smem: Ah/Al 64x40 x2 + Bh/Bl 32x136 x2 + Cs 64x136 = 90112 B (2 CTA/SM).
// ---------------------------------------------------------------------------
template<int ACT, int ROUND>
__global__ void __launch_bounds__(256) gemm_x3_kernel(
    const float* __restrict__ A, const float* __restrict__ B,
    const float* __restrict__ bias, float* __restrict__ C)
{
    extern __shared__ float sm[];
    float (*Ah)[40]  = (float(*)[40]) (sm);
    float (*Al)[40]  = (float(*)[40]) (sm + 2560);
    float (*Bh)[136] = (float(*)[136])(sm + 5120);
    float (*Bl)[136] = (float(*)[136])(sm + 9472);
    float (*Cs)[136] = (float(*)[136])(sm + 13824);

    const int tid = threadIdx.x;
    const int w = tid >> 5, wm = w >> 1, wn = w & 1;
    const int bm = blockIdx.x * 64, bn = blockIdx.y * 128;

    FragC acc[4];
    #pragma unroll
    for (int i = 0; i < 4; i++) wmma::fill_fragment(acc[i], 0.f);

    // A loader: idx = tid + p*256 -> r = idx>>3 (0..63), c4 = (idx&7)*4
    // B loader: idx = tid + p*256 -> r = idx>>5 (0..31), c4 = (idx&31)*4
    float4 apre[2], bpre[4];
    #pragma unroll
    for (int p = 0; p < 2; p++) {
        int idx = tid + p*256, r = idx >> 3, c4 = (idx & 7) * 4;
        apre[p] = *(const float4*)&A[(size_t)(bm + r)*DIM + c4];
    }
    #pragma unroll
    for (int p = 0; p < 4; p++) {
        int idx = tid + p*256, r = idx >> 5, c4 = (idx & 31) * 4;
        bpre[p] = *(const float4*)&B[(size_t)r*DIM + bn + c4];
    }

    #pragma unroll 1
    for (int kt = 0; kt < 16; kt++) {
        if (kt > 0) __syncthreads();
        // split + store current chunk
        #pragma unroll
        for (int p = 0; p < 2; p++) {
            int idx = tid + p*256, r = idx >> 3, c4 = (idx & 7) * 4;
            float vv[4] = {apre[p].x, apre[p].y, apre[p].z, apre[p].w};
            #pragma unroll
            for (int e = 0; e < 4; e++) {
                float h = wmma::__float_to_tf32(vv[e]);
                Ah[r][c4+e] = h;
                Al[r][c4+e] = wmma::__float_to_tf32(vv[e] - h);
            }
        }
        #pragma unroll
        for (int p = 0; p < 4; p++) {
            int idx = tid + p*256, r = idx >> 5, c4 = (idx & 31) * 4;
            float vv[4] = {bpre[p].x, bpre[p].y, bpre[p].z, bpre[p].w};
            #pragma unroll
            for (int e = 0; e < 4; e++) {
                float h = wmma::__float_to_tf32(vv[e]);
                Bh[r][c4+e] = h;
                Bl[r][c4+e] = wmma::__float_to_tf32(vv[e] - h);
            }
        }
        __syncthreads();
        // prefetch next chunk (overlaps with compute below)
        if (kt < 15) {
            #pragma unroll
            for (int p = 0; p < 2; p++) {
                int idx = tid + p*256, r = idx >> 3, c4 = (idx & 7) * 4;
                apre[p] = *(const float4*)&A[(size_t)(bm + r)*DIM + (kt+1)*32 + c4];
            }
            #pragma unroll
            for (int p = 0; p < 4; p++) {
                int idx = tid + p*256, r = idx >> 5, c4 = (idx & 31) * 4;
                bpre[p] = *(const float4*)&B[(size_t)((kt+1)*32 + r)*DIM + bn + c4];
            }
        }
        // compute
        #pragma unroll
        for (int ks = 0; ks < 4; ks++) {
            FragA ah, al;
            wmma::load_matrix_sync(ah, &Ah[wm*16][ks*8], 40);
            wmma::load_matrix_sync(al, &Al[wm*16][ks*8], 40);
            #pragma unroll
            for (int nf = 0; nf < 4; nf++) {
                FragB bh, bl;
                wmma::load_matrix_sync(bh, &Bh[ks*8][wn*64 + nf*16], 136);
                wmma::load_matrix_sync(bl, &Bl[ks*8][wn*64 + nf*16], 136);
                wmma::mma_sync(acc[nf], ah, bh, acc[nf]);
                wmma::mma_sync(acc[nf], al, bh, acc[nf]);
                wmma::mma_sync(acc[nf], ah, bl, acc[nf]);
            }
        }
    }

    __syncthreads();
    #pragma unroll
    for (int nf = 0; nf < 4; nf++)
        wmma::store_matrix_sync(&Cs[wm*16][wn*64 + nf*16], acc[nf], 136,
                                wmma::mem_row_major);
    __syncthreads();

    #pragma unroll
    for (int p = 0; p < 32; p++) {
        int idx = tid + p*256;
        int r = idx >> 7, c = idx & 127;
        float v = Cs[r][c] + bias[bn + c];
        if (ACT == 1) v = 0.5f * v * (1.0f + erff(v * 0.70710678118654752f));
        if (ROUND == 1) v = wmma::__float_to_tf32(v);
        C[(size_t)(bm + r)*DIM + bn + c] = v;
    }
}

// ---------------------------------------------------------------------------
// Fused retention: O = (D .* (Q @ K^T)) @ V without materializing inter.
// One CTA per 64-row Q block; 512 threads, 16 warps (warp grid 4x4).
// Q/K/V arrive pre-rounded to tf32; S rounded once during the D pass.
// K chunks double-buffered via register prefetch.
// Dynamic smem: Qf 64x520 + Ks[2]64x72 + Ss 64x72 + Vs 16x520 = 221696 B.
// ---------------------------------------------------------------------------
__global__ void __launch_bounds__(512) retention_kernel(
    const float* __restrict__ Q, const float* __restrict__ Kmat,
    const float* __restrict__ V, const float* __restrict__ D,
    float* __restrict__ O)
{
    extern __shared__ float sm[];
    float (*Qf)[520]    = (float(*)[520])   (sm);           // 33280 floats
    float (*Ks)[64][72] = (float(*)[64][72])(sm + 33280);   //  9216
    float (*Ss)[72]     = (float(*)[72])    (sm + 42496);   //  4608
    float (*Vs)[520]    = (float(*)[520])   (sm + 47104);   //  8320

    const int tid = threadIdx.x;
    const int w = tid >> 5, wm = w >> 2, wn = w & 3;
    const int i0 = blockIdx.x * 64;

    // Load full Q tile (64 x 512), already tf32-rounded by producer.
    #pragma unroll
    for (int p = 0; p < 16; p++) {
        int idx = tid + p*512;
        int r = idx >> 7, c4 = (idx & 127) * 4;
        *(float4*)&Qf[r][c4] = *(const float4*)&Q[(size_t)(i0 + r)*DIM + c4];
    }

    FragC o[8];
    #pragma unroll
    for (int i = 0; i < 8; i++) wmma::fill_fragment(o[i], 0.f);

    #pragma unroll 1
    for (int j0 = 0; j0 < NROWS; j0 += 64) {
        // ---- S = Q_tile @ K_j^T (64x64), each warp one 16x16 tile ----
        FragC s;
        wmma::fill_fragment(s, 0.f);

        float4 kpre[2];
        #pragma unroll
        for (int p = 0; p < 2; p++) {
            int idx = tid + p*512, r = idx >> 4, c4 = (idx & 15) * 4;
            kpre[p] = *(const float4*)&Kmat[(size_t)(j0 + r)*DIM + c4];
        }
        #pragma unroll
        for (int p = 0; p < 2; p++) {
            int idx = tid + p*512, r = idx >> 4, c4 = (idx & 15) * 4;
            *(float4*)&Ks[0][r][c4] = kpre[p];
        }
        __syncthreads();

        #pragma unroll 1
        for (int c = 0; c < 8; c++) {
            int buf = c & 1;
            if (c < 7) {
                #pragma unroll
                for (int p = 0; p < 2; p++) {
                    int idx = tid + p*512, r = idx >> 4, c4 = (idx & 15) * 4;
                    kpre[p] = *(const float4*)&Kmat[(size_t)(j0 + r)*DIM + (c+1)*64 + c4];
                }
            }
            #pragma unroll
            for (int ks = 0; ks < 8; ks++) {
                FragA a;
                wmma::load_matrix_sync(a, &Qf[wm*16][c*64 + ks*8], 520);
                FragBT b;   // B[k][n] = K[j0 + wn*16 + n][...] -> col-major on Ks rows
                wmma::load_matrix_sync(b, &Ks[buf][wn*16][ks*8], 72);
                wmma::mma_sync(s, a, b, s);
            }
            if (c < 7) {
                #pragma unroll
                for (int p = 0; p < 2; p++) {
                    int idx = tid + p*512, r = idx >> 4, c4 = (idx & 15) * 4;
                    *(float4*)&Ks[buf ^ 1][r][c4] = kpre[p];
                }
            }
            __syncthreads();
        }

        wmma::store_matrix_sync(&Ss[wm*16][wn*16], s, 72, wmma::mem_row_major);
        __syncthreads();

        // ---- S *= D tile; round once to tf32 ----
        #pragma unroll
        for (int q = 0; q < 8; q++) {
            int idx = tid + q*512;
            int r = idx >> 6, cc = idx & 63;
            float v = Ss[r][cc] * D[(size_t)(i0 + r)*NROWS + j0 + cc];
            Ss[r][cc] = wmma::__float_to_tf32(v);
        }
        __syncthreads();

        // ---- O += S_d (64x64) @ V_j (64x512); each warp 16x128 of O ----
        #pragma unroll 1
        for (int kc = 0; kc < 4; kc++) {
            if (kc > 0) __syncthreads();
            #pragma unroll
            for (int p = 0; p < 4; p++) {
                int idx = tid + p*512;
                int r = idx >> 7, c4 = (idx & 127) * 4;
                *(float4*)&Vs[r][c4] =
                    *(const float4*)&V[(size_t)(j0 + kc*16 + r)*DIM + c4];
            }
            __syncthreads();
            #pragma unroll
            for (int ks = 0; ks < 2; ks++) {
                FragA a;
                wmma::load_matrix_sync(a, &Ss[wm*16][kc*16 + ks*8], 72);
                #pragma unroll
                for (int nf = 0; nf < 8; nf++) {
                    FragB b;
                    wmma::load_matrix_sync(b, &Vs[ks*8][wn*128 + nf*16], 520);
                    wmma::mma_sync(o[nf], a, b, o[nf]);
                }
            }
        }
        __syncthreads();
    }

    #pragma unroll
    for (int nf = 0; nf < 8; nf++)
        wmma::store_matrix_sync(&O[(size_t)(i0 + wm*16)*DIM + wn*128 + nf*16],
                                o[nf], DIM, wmma::mem_row_major);
}

// ---------------------------------------------------------------------------
// GroupNorm over 16 groups of 32 channels, per row, in-place on d_out.
// ---------------------------------------------------------------------------
__global__ void groupnorm_kernel(float* __restrict__ out,
                                 const float* __restrict__ gamma,
                                 const float* __restrict__ beta)
{
    __shared__ float buf[512];
    __shared__ float smu[16], siv[16];
    const int row = blockIdx.x;
    const int tid = threadIdx.x;  // 256
    float* p = out + (size_t)row * DIM;
    buf[tid]       = p[tid];
    buf[tid + 256] = p[tid + 256];
    __syncthreads();
    if (tid < 16) {
        float s = 0.f, s2 = 0.f;
        #pragma unroll
        for (int c = 0; c < 32; c++) {
            float v = buf[tid*32 + c];
            s += v; s2 += v*v;
        }
        float mu  = s  * (1.f/32.f);
        float var = s2 * (1.f/32.f) - mu*mu;
        smu[tid] = mu;
        siv[tid] = rsqrtf(var + 1e-5f);
    }
    __syncthreads();
    #pragma unroll
    for (int q = 0; q < 2; q++) {
        int c = tid + q*256;
        int g = c >> 5;
        p[c] = (buf[c] - smu[g]) * siv[g] * gamma[c] + beta[c];
    }
}

// ---------------------------------------------------------------------------
extern "C" void kernel_launch(void* const* d_in, const int* in_sizes, int n_in,
                              void* d_out, int out_size)
{
    const float* x     = (const float*)d_in[0];
    const float* D     = (const float*)d_in[1];
    const float* Wq    = (const float*)d_in[2];
    const float* bq    = (const float*)d_in[3];
    const float* Wk    = (const float*)d_in[4];
    const float* bk    = (const float*)d_in[5];
    const float* Wv    = (const float*)d_in[6];
    const float* bv    = (const float*)d_in[7];
    const float* Wf    = (const float*)d_in[8];
    const float* bf    = (const float*)d_in[9];
    const float* Wp    = (const float*)d_in[10];
    const float* bp    = (const float*)d_in[11];
    const float* gamma = (const float*)d_in[12];
    const float* beta  = (const float*)d_in[13];
    float* out = (float*)d_out;

    float *Q, *K, *V, *XR, *H;
    cudaGetSymbolAddress((void**)&Q,  g_Q);
    cudaGetSymbolAddress((void**)&K,  g_K);
    cudaGetSymbolAddress((void**)&V,  g_V);
    cudaGetSymbolAddress((void**)&XR, g_XR);
    cudaGetSymbolAddress((void**)&H,  g_H);

    const int GEMM_SMEM = 90112;
    const int RET_SMEM  = 221696;
    cudaFuncSetAttribute(gemm_x3_kernel<0,1>,
                         cudaFuncAttributeMaxDynamicSharedMemorySize, GEMM_SMEM);
    cudaFuncSetAttribute(gemm_x3_kernel<1,0>,
                         cudaFuncAttributeMaxDynamicSharedMemorySize, GEMM_SMEM);
    cudaFuncSetAttribute(gemm_x3_kernel<0,0>,
                         cudaFuncAttributeMaxDynamicSharedMemorySize, GEMM_SMEM);
    cudaFuncSetAttribute(retention_kernel,
                         cudaFuncAttributeMaxDynamicSharedMemorySize, RET_SMEM);

    dim3 gs(NROWS/64, DIM/128);   // 128 x 4
    gemm_x3_kernel<0,1><<<gs, 256, GEMM_SMEM>>>(x, Wq, bq, Q);
    gemm_x3_kernel<0,1><<<gs, 256, GEMM_SMEM>>>(x, Wk, bk, K);
    gemm_x3_kernel<0,1><<<gs, 256, GEMM_SMEM>>>(x, Wv, bv, V);

    retention_kernel<<<NROWS/64, 512, RET_SMEM>>>(Q, K, V, D, XR);

    gemm_x3_kernel<1,0><<<gs, 256, GEMM_SMEM>>>(XR, Wf, bf, H);    // + exact GELU
    gemm_x3_kernel<0,0><<<gs, 256, GEMM_SMEM>>>(H,  Wp, bp, out);

    groupnorm_kernel<<<NROWS, 256>>>(out, gamma, beta);
}

// round 5
// speedup vs baseline: 2.3546x; 2.3546x over previous
#include <cuda_runtime.h>
#include <mma.h>
#include <math.h>
#include <stdint.h>

#define NROWS 8192
#define DIM 512

__device__ float g_Q [NROWS*DIM];
__device__ float g_K [NROWS*DIM];
__device__ float g_V [NROWS*DIM];
__device__ float g_XR[NROWS*DIM];
__device__ float g_H [NROWS*DIM];

__device__ __forceinline__ float tf32r(float v) { return nvcuda::wmma::__float_to_tf32(v); }

// mma.m16n8k8 tf32: D += A*B. a[4], b[2] hold tf32-rounded fp32 bit patterns.
__device__ __forceinline__ void mma8(float* c, const float* a, const float* b) {
    asm volatile("mma.sync.aligned.m16n8k8.row.col.f32.tf32.tf32.f32 "
        "{%0,%1,%2,%3}, {%4,%5,%6,%7}, {%8,%9}, {%0,%1,%2,%3};"
        : "+f"(c[0]), "+f"(c[1]), "+f"(c[2]), "+f"(c[3])
        : "r"(__float_as_uint(a[0])), "r"(__float_as_uint(a[1])),
          "r"(__float_as_uint(a[2])), "r"(__float_as_uint(a[3])),
          "r"(__float_as_uint(b[0])), "r"(__float_as_uint(b[1])));
}

// ===========================================================================
// Retention: O = (D .* (Q K^T)) @ V.  CTA = 64 Q-rows, 256 thr (8 warps).
// j-chunks of 128.  QK: S 64x128, warps 2x4, warp tile 32x32.
//                   SV: O 64x512, warps 2x4, warp tile 32x128.
// smem(floats): Qf[64][516]=33024 | Ks[128][36]=4608 | Ss[64][132]=8448 |
//               Vs[2][8][520]=8320  -> 54400 fl = 217600 B
// ===========================================================================
#define RET_SMEM 217600

__global__ void __launch_bounds__(256, 1) retention_mma(
    const float* __restrict__ Q, const float* __restrict__ K,
    const float* __restrict__ V, const float* __restrict__ D,
    float* __restrict__ O)
{
    extern __shared__ float sm[];
    float (*Qf)[516]     = (float(*)[516])    sm;            // 33024
    float (*Ks)[36]      = (float(*)[36])    (sm + 33024);   //  4608
    float (*Ss)[132]     = (float(*)[132])   (sm + 37632);   //  8448
    float (*Vs)[8][520]  = (float(*)[8][520])(sm + 46080);   //  8320

    const int tid = threadIdx.x;
    const int lane = tid & 31, w = tid >> 5;
    const int wm = w >> 2, wn = w & 3;     // 2 x 4 warp grid
    const int qr = lane >> 2, qc = lane & 3;
    const int i0 = blockIdx.x * 64;

    // Q tile resident (producer already tf32-rounded)
    #pragma unroll
    for (int p = 0; p < 32; p++) {
        int idx = tid + p*256, r = idx >> 7, c4 = (idx & 127) * 4;
        *(float4*)&Qf[r][c4] = *(const float4*)&Q[(size_t)(i0 + r)*DIM + c4];
    }

    float o[2][16][4];
    #pragma unroll
    for (int f = 0; f < 2; f++)
        #pragma unroll
        for (int g = 0; g < 16; g++)
            #pragma unroll
            for (int e = 0; e < 4; e++) o[f][g][e] = 0.f;

    #pragma unroll 1
    for (int j0 = 0; j0 < NROWS; j0 += 128) {
        // ---------------- QK:  S = Q @ K[j0:j0+128]^T ----------------
        float s[2][4][4];
        #pragma unroll
        for (int f = 0; f < 2; f++)
            #pragma unroll
            for (int g = 0; g < 4; g++)
                #pragma unroll
                for (int e = 0; e < 4; e++) s[f][g][e] = 0.f;

        float4 kp[4];
        #pragma unroll
        for (int p = 0; p < 4; p++) {
            int idx = tid + p*256, r = idx >> 3, c4 = (idx & 7) * 4;
            kp[p] = *(const float4*)&K[(size_t)(j0 + r)*DIM + c4];
        }
        #pragma unroll
        for (int p = 0; p < 4; p++) {
            int idx = tid + p*256, r = idx >> 3, c4 = (idx & 7) * 4;
            *(float4*)&Ks[r][c4] = kp[p];
        }
        __syncthreads();

        #pragma unroll 1
        for (int kc = 0; kc < 16; kc++) {
            if (kc < 15) {
                #pragma unroll
                for (int p = 0; p < 4; p++) {
                    int idx = tid + p*256, r = idx >> 3, c4 = (idx & 7) * 4;
                    kp[p] = *(const float4*)&K[(size_t)(j0 + r)*DIM + (kc+1)*32 + c4];
                }
            }
            #pragma unroll
            for (int k8 = 0; k8 < 4; k8++) {
                const int kq = kc*32 + k8*8 + qc;
                const int kk = k8*8 + qc;
                float a[2][4];
                #pragma unroll
                for (int f = 0; f < 2; f++) {
                    int rb = wm*32 + f*16 + qr;
                    a[f][0] = Qf[rb][kq];     a[f][1] = Qf[rb+8][kq];
                    a[f][2] = Qf[rb][kq+4];   a[f][3] = Qf[rb+8][kq+4];
                }
                #pragma unroll
                for (int g = 0; g < 4; g++) {
                    int nb = wn*32 + g*8 + qr;
                    float b[2] = { Ks[nb][kk], Ks[nb][kk+4] };
                    mma8(s[0][g], a[0], b);
                    mma8(s[1][g], a[1], b);
                }
            }
            __syncthreads();
            if (kc < 15) {
                #pragma unroll
                for (int p = 0; p < 4; p++) {
                    int idx = tid + p*256, r = idx >> 3, c4 = (idx & 7) * 4;
                    *(float4*)&Ks[r][c4] = kp[p];
                }
                __syncthreads();
            }
        }

        // ------------- apply D on fragments, round, stage Ss -------------
        #pragma unroll
        for (int f = 0; f < 2; f++)
            #pragma unroll
            for (int g = 0; g < 4; g++) {
                int r = wm*32 + f*16 + qr;
                int c = wn*32 + g*8 + 2*qc;
                float2 d0 = *(const float2*)&D[(size_t)(i0 + r)*NROWS + j0 + c];
                float2 d1 = *(const float2*)&D[(size_t)(i0 + r + 8)*NROWS + j0 + c];
                Ss[r][c]     = tf32r(s[f][g][0] * d0.x);
                Ss[r][c+1]   = tf32r(s[f][g][1] * d0.y);
                Ss[r+8][c]   = tf32r(s[f][g][2] * d1.x);
                Ss[r+8][c+1] = tf32r(s[f][g][3] * d1.y);
            }

        // stage 0 of V
        float4 vp[4];
        #pragma unroll
        for (int p = 0; p < 4; p++) {
            int idx = tid + p*256, r = idx >> 7, c4 = (idx & 127) * 4;
            vp[p] = *(const float4*)&V[(size_t)(j0 + r)*DIM + c4];
        }
        #pragma unroll
        for (int p = 0; p < 4; p++) {
            int idx = tid + p*256, r = idx >> 7, c4 = (idx & 127) * 4;
            *(float4*)&Vs[0][r][c4] = vp[p];
        }
        __syncthreads();

        // ------------- SV:  O += Ss @ V[j0:j0+128]  (16 stages) -------------
        #pragma unroll 1
        for (int st = 0; st < 16; st++) {
            const int buf = st & 1;
            if (st < 15) {
                #pragma unroll
                for (int p = 0; p < 4; p++) {
                    int idx = tid + p*256, r = idx >> 7, c4 = (idx & 127) * 4;
                    vp[p] = *(const float4*)&V[(size_t)(j0 + (st+1)*8 + r)*DIM + c4];
                }
            }
            const int k = st*8 + qc;
            float a[2][4];
            #pragma unroll
            for (int f = 0; f < 2; f++) {
                int rb = wm*32 + f*16 + qr;
                a[f][0] = Ss[rb][k];     a[f][1] = Ss[rb+8][k];
                a[f][2] = Ss[rb][k+4];   a[f][3] = Ss[rb+8][k+4];
            }
            #pragma unroll
            for (int g = 0; g < 16; g++) {
                int n = wn*128 + g*8 + qr;
                float b[2] = { Vs[buf][qc][n], Vs[buf][qc+4][n] };
                mma8(o[0][g], a[0], b);
                mma8(o[1][g], a[1], b);
            }
            if (st < 15) {
                #pragma unroll
                for (int p = 0; p < 4; p++) {
                    int idx = tid + p*256, r = idx >> 7, c4 = (idx & 127) * 4;
                    *(float4*)&Vs[buf ^ 1][r][c4] = vp[p];
                }
                __syncthreads();
            }
        }
        __syncthreads();
    }

    // ---------------- epilogue ----------------
    #pragma unroll
    for (int f = 0; f < 2; f++)
        #pragma unroll
        for (int g = 0; g < 16; g++) {
            int r = i0 + wm*32 + f*16 + qr;
            int c = wn*128 + g*8 + 2*qc;
            *(float2*)&O[(size_t)r*DIM + c]       = make_float2(o[f][g][0], o[f][g][1]);
            *(float2*)&O[(size_t)(r + 8)*DIM + c] = make_float2(o[f][g][2], o[f][g][3]);
        }
}

// ===========================================================================
// Small GEMMs (tf32x3): C = act(A @ B + bias).  BM=128, BN=64, BK=32.
// 256 thr, warps 4(m) x 2(n), warp tile 32x32.  hi/lo split at SMEM store.
// smem: Ah/Al[128][36] + Bh/Bl[32][72] = 13824 fl = 55296 B.
// ===========================================================================
#define GEMM_SMEM 55296

template<int ACT, int ROUND>
__global__ void __launch_bounds__(256) gemm_x3(
    const float* __restrict__ A, const float* __restrict__ B,
    const float* __restrict__ bias, float* __restrict__ C)
{
    extern __shared__ float sm[];
    float (*Ah)[36] = (float(*)[36]) sm;            // 4608
    float (*Al)[36] = (float(*)[36])(sm + 4608);    // 4608
    float (*Bh)[72] = (float(*)[72])(sm + 9216);    // 2304
    float (*Bl)[72] = (float(*)[72])(sm + 11520);   // 2304

    const int tid = threadIdx.x;
    const int lane = tid & 31, w = tid >> 5;
    const int wm = w >> 1, wn = w & 1;              // 4 x 2
    const int qr = lane >> 2, qc = lane & 3;
    const int bm = blockIdx.x * 128, bn = blockIdx.y * 64;

    float acc[2][4][4];
    #pragma unroll
    for (int f = 0; f < 2; f++)
        #pragma unroll
        for (int g = 0; g < 4; g++)
            #pragma unroll
            for (int e = 0; e < 4; e++) acc[f][g][e] = 0.f;

    float4 ap[4]; float4 bp[2];
    #pragma unroll
    for (int p = 0; p < 4; p++) {
        int idx = tid + p*256, r = idx >> 3, c4 = (idx & 7) * 4;
        ap[p] = *(const float4*)&A[(size_t)(bm + r)*DIM + c4];
    }
    #pragma unroll
    for (int p = 0; p < 2; p++) {
        int idx = tid + p*256, r = idx >> 4, c4 = (idx & 15) * 4;
        bp[p] = *(const float4*)&B[(size_t)r*DIM + bn + c4];
    }

    #pragma unroll 1
    for (int kc = 0; kc < 16; kc++) {
        // split + store current chunk
        #pragma unroll
        for (int p = 0; p < 4; p++) {
            int idx = tid + p*256, r = idx >> 3, c4 = (idx & 7) * 4;
            float vv[4] = {ap[p].x, ap[p].y, ap[p].z, ap[p].w};
            #pragma unroll
            for (int e = 0; e < 4; e++) {
                float h = tf32r(vv[e]);
                Ah[r][c4+e] = h;
                Al[r][c4+e] = tf32r(vv[e] - h);
            }
        }
        #pragma unroll
        for (int p = 0; p < 2; p++) {
            int idx = tid + p*256, r = idx >> 4, c4 = (idx & 15) * 4;
            float vv[4] = {bp[p].x, bp[p].y, bp[p].z, bp[p].w};
            #pragma unroll
            for (int e = 0; e < 4; e++) {
                float h = tf32r(vv[e]);
                Bh[r][c4+e] = h;
                Bl[r][c4+e] = tf32r(vv[e] - h);
            }
        }
        __syncthreads();
        if (kc < 15) {
            #pragma unroll
            for (int p = 0; p < 4; p++) {
                int idx = tid + p*256, r = idx >> 3, c4 = (idx & 7) * 4;
                ap[p] = *(const float4*)&A[(size_t)(bm + r)*DIM + (kc+1)*32 + c4];
            }
            #pragma unroll
            for (int p = 0; p < 2; p++) {
                int idx = tid + p*256, r = idx >> 4, c4 = (idx & 15) * 4;
                bp[p] = *(const float4*)&B[(size_t)((kc+1)*32 + r)*DIM + bn + c4];
            }
        }
        #pragma unroll
        for (int k8 = 0; k8 < 4; k8++) {
            const int kk = k8*8 + qc;
            float ah[2][4], al[2][4];
            #pragma unroll
            for (int f = 0; f < 2; f++) {
                int rb = wm*32 + f*16 + qr;
                ah[f][0] = Ah[rb][kk];   ah[f][1] = Ah[rb+8][kk];
                ah[f][2] = Ah[rb][kk+4]; ah[f][3] = Ah[rb+8][kk+4];
                al[f][0] = Al[rb][kk];   al[f][1] = Al[rb+8][kk];
                al[f][2] = Al[rb][kk+4]; al[f][3] = Al[rb+8][kk+4];
            }
            #pragma unroll
            for (int g = 0; g < 4; g++) {
                int n = wn*32 + g*8 + qr;
                float bh[2] = { Bh[kk][n], Bh[kk+4 - qc + qc][n] };  // placeholder fix below
                bh[0] = Bh[k8*8 + qc][n];
                bh[1] = Bh[k8*8 + qc + 4][n];
                float bl[2] = { Bl[k8*8 + qc][n], Bl[k8*8 + qc + 4][n] };
                #pragma unroll
                for (int f = 0; f < 2; f++) {
                    mma8(acc[f][g], ah[f], bh);
                    mma8(acc[f][g], al[f], bh);
                    mma8(acc[f][g], ah[f], bl);
                }
            }
        }
        __syncthreads();
    }

    // epilogue: bias + act, direct global stores
    #pragma unroll
    for (int f = 0; f < 2; f++)
        #pragma unroll
        for (int g = 0; g < 4; g++) {
            int r = bm + wm*32 + f*16 + qr;
            int c = bn + wn*32 + g*8 + 2*qc;
            float2 bb = *(const float2*)&bias[c];
            float v0 = acc[f][g][0] + bb.x, v1 = acc[f][g][1] + bb.y;
            float v2 = acc[f][g][2] + bb.x, v3 = acc[f][g][3] + bb.y;
            if (ACT == 1) {
                v0 = 0.5f*v0*(1.f + erff(v0*0.70710678118654752f));
                v1 = 0.5f*v1*(1.f + erff(v1*0.70710678118654752f));
                v2 = 0.5f*v2*(1.f + erff(v2*0.70710678118654752f));
                v3 = 0.5f*v3*(1.f + erff(v3*0.70710678118654752f));
            }
            if (ROUND == 1) { v0 = tf32r(v0); v1 = tf32r(v1); v2 = tf32r(v2); v3 = tf32r(v3); }
            *(float2*)&C[(size_t)r*DIM + c]       = make_float2(v0, v1);
            *(float2*)&C[(size_t)(r + 8)*DIM + c] = make_float2(v2, v3);
        }
}

// ---------------------------------------------------------------------------
__global__ void groupnorm_kernel(float* __restrict__ out,
                                 const float* __restrict__ gamma,
                                 const float* __restrict__ beta)
{
    __shared__ float buf[512];
    __shared__ float smu[16], siv[16];
    const int row = blockIdx.x;
    const int tid = threadIdx.x;
    float* p = out + (size_t)row * DIM;
    buf[tid]       = p[tid];
    buf[tid + 256] = p[tid + 256];
    __syncthreads();
    if (tid < 16) {
        float sx = 0.f, s2 = 0.f;
        #pragma unroll
        for (int c = 0; c < 32; c++) { float v = buf[tid*32 + c]; sx += v; s2 += v*v; }
        float mu  = sx * (1.f/32.f);
        float var = s2 * (1.f/32.f) - mu*mu;
        smu[tid] = mu;
        siv[tid] = rsqrtf(var + 1e-5f);
    }
    __syncthreads();
    #pragma unroll
    for (int q = 0; q < 2; q++) {
        int c = tid + q*256;
        int g = c >> 5;
        p[c] = (buf[c] - smu[g]) * siv[g] * gamma[c] + beta[c];
    }
}

// ---------------------------------------------------------------------------
extern "C" void kernel_launch(void* const* d_in, const int* in_sizes, int n_in,
                              void* d_out, int out_size)
{
    const float* x     = (const float*)d_in[0];
    const float* D     = (const float*)d_in[1];
    const float* Wq    = (const float*)d_in[2];
    const float* bq    = (const float*)d_in[3];
    const float* Wk    = (const float*)d_in[4];
    const float* bk    = (const float*)d_in[5];
    const float* Wv    = (const float*)d_in[6];
    const float* bv    = (const float*)d_in[7];
    const float* Wf    = (const float*)d_in[8];
    const float* bf    = (const float*)d_in[9];
    const float* Wp    = (const float*)d_in[10];
    const float* bp    = (const float*)d_in[11];
    const float* gamma = (const float*)d_in[12];
    const float* beta  = (const float*)d_in[13];
    float* out = (float*)d_out;

    float *Q, *K, *V, *XR, *H;
    cudaGetSymbolAddress((void**)&Q,  g_Q);
    cudaGetSymbolAddress((void**)&K,  g_K);
    cudaGetSymbolAddress((void**)&V,  g_V);
    cudaGetSymbolAddress((void**)&XR, g_XR);
    cudaGetSymbolAddress((void**)&H,  g_H);

    cudaFuncSetAttribute(gemm_x3<0,1>,
                         cudaFuncAttributeMaxDynamicSharedMemorySize, GEMM_SMEM);
    cudaFuncSetAttribute(gemm_x3<1,0>,
                         cudaFuncAttributeMaxDynamicSharedMemorySize, GEMM_SMEM);
    cudaFuncSetAttribute(gemm_x3<0,0>,
                         cudaFuncAttributeMaxDynamicSharedMemorySize, GEMM_SMEM);
    cudaFuncSetAttribute(retention_mma,
                         cudaFuncAttributeMaxDynamicSharedMemorySize, RET_SMEM);

    dim3 gs(NROWS/128, DIM/64);    // 64 x 8
    gemm_x3<0,1><<<gs, 256, GEMM_SMEM>>>(x, Wq, bq, Q);
    gemm_x3<0,1><<<gs, 256, GEMM_SMEM>>>(x, Wk, bk, K);
    gemm_x3<0,1><<<gs, 256, GEMM_SMEM>>>(x, Wv, bv, V);

    retention_mma<<<NROWS/64, 256, RET_SMEM>>>(Q, K, V, D, XR);

    gemm_x3<1,0><<<gs, 256, GEMM_SMEM>>>(XR, Wf, bf, H);   // exact GELU
    gemm_x3<0,0><<<gs, 256, GEMM_SMEM>>>(H,  Wp, bp, out);

    groupnorm_kernel<<<NROWS, 256>>>(out, gamma, beta);
}